// round 16
// baseline (speedup 1.0000x reference)
#include <cuda_runtime.h>
#include <cuda_bf16.h>
#include <cuda_fp16.h>
#include <cstdint>
#include <mma.h>

using namespace nvcuda;
typedef __nv_bfloat16 bf16;

#define NN 100000
#define NNPAD 100096   // 782 * 128
#define EE 1600000
#define INDIM 64
#define HDDIM 128

// ---------------- scratch (static device globals; no allocation) ----------------
__device__ float g_feat [NNPAD * HDDIM];
__device__ __half g_feath[NN * HDDIM];   // fp16 shadow of feat for the gather pass
__device__ float g_el   [NN * 2];
__device__ float g_er   [NN * 2];
__device__ float g_h0   [NN * HDDIM];
__device__ float g_h1   [NN * HDDIM];
__device__ float g_rep0 [NNPAD * INDIM];
__device__ float g_r0   [NN * HDDIM];
__device__ float g_accb [NN * HDDIM];
__device__ int   g_ptr  [NN + 1];
__device__ int   g_cnt  [NN];      // zero at load; every call leaves it zero
__device__ int   g_csrc [EE];
__device__ int   g_rflag[NN];      // bits 0-2: decoder iter remask; bit 3: encoder mask. zero at load & after each call.

// ---------------- prep: edge histogram + all mask flags in one launch ----------------
__global__ void prep_kernel(const int* __restrict__ dst,
                            const int* __restrict__ encm, int encCnt,
                            const int* __restrict__ remask, int remaskCnt) {
    int i = blockIdx.x * blockDim.x + threadIdx.x;
    if (i < EE) atomicAdd(&g_cnt[dst[i]], 1);
    if (i < encCnt) atomicOr(&g_rflag[encm[i]], 8);
    if (i < 3 * remaskCnt) atomicOr(&g_rflag[remask[i]], 1 << (i / remaskCnt));
}

// exclusive-scan degrees into g_ptr, re-zero g_cnt for scatter
__global__ void scan_kernel() {
    const int T = 1024;
    const int CH = (NN + T - 1) / T;
    __shared__ int ss[T];
    int t = threadIdx.x;
    int lo = t * CH;
    int hi = lo + CH; if (hi > NN) hi = NN;
    int s = 0;
    for (int i = lo; i < hi; i++) s += g_cnt[i];
    ss[t] = s;
    __syncthreads();
    for (int off = 1; off < T; off <<= 1) {
        int v = (t >= off) ? ss[t - off] : 0;
        __syncthreads();
        ss[t] += v;
        __syncthreads();
    }
    int run = (t == 0) ? 0 : ss[t - 1];
    for (int i = lo; i < hi; i++) { g_ptr[i] = run; run += g_cnt[i]; g_cnt[i] = 0; }
    if (t == 0) g_ptr[NN] = ss[T - 1];
}

__global__ void scatter_kernel(const int* __restrict__ src, const int* __restrict__ dst) {
    int i = blockIdx.x * blockDim.x + threadIdx.x;
    if (i < EE) {
        int d = dst[i];
        int off = atomicAdd(&g_cnt[d], 1);
        g_csrc[g_ptr[d] + off] = src[i];
    }
}

// tail: restore g_cnt and g_rflag to zero for the next call
__global__ void cleanup_kernel() {
    int i = blockIdx.x * blockDim.x + threadIdx.x;
    if (i < NN) { g_cnt[i] = 0; g_rflag[i] = 0; }
}

// ---------------- bf16 split helper: v = hi + lo + O(2^-18 v) ----------------
__device__ __forceinline__ void split_bf16(float v, bf16& h, bf16& l) {
    h = __float2bfloat16_rn(v);
    l = __float2bfloat16_rn(v - __bfloat162float(h));
}

// ---------------- fused GEMM + elr: feat = A@W (bf16 3-term), el/er logits, fp16 shadow ----------------
// BN = 128 fixed. Optional per-row token substitution via g_rflag bit `iter`.
template <int K, bool REMASK>
__global__ __launch_bounds__(256) void gemm_elr_kernel(
    const float* __restrict__ A, const float* __restrict__ W,
    const float* __restrict__ al, const float* __restrict__ ar,
    const float* __restrict__ token, int iter,
    float* __restrict__ outF, float* __restrict__ el, float* __restrict__ er,
    __half* __restrict__ feath)
{
    constexpr int BM = 128, BN = 128, KB = 32;
    constexpr int ASTR = KB + 8;    // 40
    constexpr int WSTR = BN + 8;    // 136
    constexpr int WM = 64, WN = 32, AR = 4, AC = 2;
    constexpr int AS_ELEMS = BM * ASTR;
    constexpr int WS_ELEMS = KB * WSTR;

    extern __shared__ __align__(32) char sraw[];
    bf16* AsH = (bf16*)sraw;
    bf16* AsL = AsH + AS_ELEMS;
    bf16* WsH = AsL + AS_ELEMS;
    bf16* WsL = WsH + WS_ELEMS;

    int tid = threadIdx.x;
    int wid = tid >> 5;
    int lane = tid & 31;
    int wy = wid >> 2;
    int wx = wid & 3;
    long n0 = (long)blockIdx.x * BM;

    wmma::fragment<wmma::accumulator, 16, 16, 16, float> acc[AR][AC];
#pragma unroll
    for (int r = 0; r < AR; r++)
#pragma unroll
        for (int c = 0; c < AC; c++)
            wmma::fill_fragment(acc[r][c], 0.0f);

    for (int kb = 0; kb < K; kb += KB) {
#pragma unroll
        for (int it = 0; it < 4; it++) {
            int f4  = tid + it * 256;
            int row = f4 >> 3;
            int c4  = f4 & 7;
            long n  = n0 + row;
            float4 v = make_float4(0.f, 0.f, 0.f, 0.f);
            if (n < NN) {
                if (REMASK && ((g_rflag[n] >> iter) & 1)) {
                    v = *(const float4*)(token + kb + 4 * c4);
                } else {
                    v = *(const float4*)(A + n * K + kb + 4 * c4);
                }
            }
            bf16 h0, l0, h1, l1, h2, l2, h3, l3;
            split_bf16(v.x, h0, l0);
            split_bf16(v.y, h1, l1);
            split_bf16(v.z, h2, l2);
            split_bf16(v.w, h3, l3);
            int off = row * ASTR + 4 * c4;
            __nv_bfloat162 p;
            p.x = h0; p.y = h1; *(__nv_bfloat162*)&AsH[off]     = p;
            p.x = h2; p.y = h3; *(__nv_bfloat162*)&AsH[off + 2] = p;
            p.x = l0; p.y = l1; *(__nv_bfloat162*)&AsL[off]     = p;
            p.x = l2; p.y = l3; *(__nv_bfloat162*)&AsL[off + 2] = p;
        }
#pragma unroll
        for (int it = 0; it < 4; it++) {
            int f4  = tid + it * 256;
            int row = f4 >> 5;
            int c4  = f4 & 31;
            float4 v = *(const float4*)(W + (long)(kb + row) * BN + 4 * c4);
            bf16 h0, l0, h1, l1, h2, l2, h3, l3;
            split_bf16(v.x, h0, l0);
            split_bf16(v.y, h1, l1);
            split_bf16(v.z, h2, l2);
            split_bf16(v.w, h3, l3);
            int off = row * WSTR + 4 * c4;
            __nv_bfloat162 p;
            p.x = h0; p.y = h1; *(__nv_bfloat162*)&WsH[off]     = p;
            p.x = h2; p.y = h3; *(__nv_bfloat162*)&WsH[off + 2] = p;
            p.x = l0; p.y = l1; *(__nv_bfloat162*)&WsL[off]     = p;
            p.x = l2; p.y = l3; *(__nv_bfloat162*)&WsL[off + 2] = p;
        }
        __syncthreads();

#pragma unroll
        for (int ks = 0; ks < 2; ks++) {
            wmma::fragment<wmma::matrix_b, 16, 16, 16, bf16, wmma::row_major> bH[AC], bL[AC];
#pragma unroll
            for (int c = 0; c < AC; c++) {
                wmma::load_matrix_sync(bH[c], WsH + (ks * 16) * WSTR + wx * WN + c * 16, WSTR);
                wmma::load_matrix_sync(bL[c], WsL + (ks * 16) * WSTR + wx * WN + c * 16, WSTR);
            }
#pragma unroll
            for (int r = 0; r < AR; r++) {
                wmma::fragment<wmma::matrix_a, 16, 16, 16, bf16, wmma::row_major> aH, aL;
                wmma::load_matrix_sync(aH, AsH + (wy * WM + r * 16) * ASTR + ks * 16, ASTR);
                wmma::load_matrix_sync(aL, AsL + (wy * WM + r * 16) * ASTR + ks * 16, ASTR);
#pragma unroll
                for (int c = 0; c < AC; c++) {
                    wmma::mma_sync(acc[r][c], aH, bH[c], acc[r][c]);
                    wmma::mma_sync(acc[r][c], aH, bL[c], acc[r][c]);
                    wmma::mma_sync(acc[r][c], aL, bH[c], acc[r][c]);
                }
            }
        }
        __syncthreads();
    }

    // ---- fused epilogue: stage -> feat + fp16 shadow + el/er ----
    float* stage = (float*)sraw;
#pragma unroll
    for (int r = 0; r < AR; r++)
#pragma unroll
        for (int c = 0; c < AC; c++)
            wmma::store_matrix_sync(stage + (wy * WM + r * 16) * BN + wx * WN + c * 16,
                                    acc[r][c], BN, wmma::mem_row_major);
    __syncthreads();

    float4 a4 = *(const float4*)(al + 4 * lane);
    float4 r4 = *(const float4*)(ar + 4 * lane);
#pragma unroll 4
    for (int rr = 0; rr < 16; rr++) {
        int row = wid * 16 + rr;
        long n = n0 + row;
        float4 f = *(float4*)(stage + row * BN + 4 * lane);
        *(float4*)(outF + n * BN + 4 * lane) = f;          // feat padded to NNPAD: unguarded
        float ep = f.x * a4.x + f.y * a4.y + f.z * a4.z + f.w * a4.w;
        float rp = f.x * r4.x + f.y * r4.y + f.z * r4.z + f.w * r4.w;
#pragma unroll
        for (int off = 8; off; off >>= 1) {
            ep += __shfl_down_sync(0xffffffffu, ep, off, 16);
            rp += __shfl_down_sync(0xffffffffu, rp, off, 16);
        }
        if (n < NN) {
            __half2 hlo = __floats2half2_rn(f.x, f.y);
            __half2 hhi = __floats2half2_rn(f.z, f.w);
            uint2 pk;
            pk.x = *(unsigned int*)&hlo;
            pk.y = *(unsigned int*)&hhi;
            *(uint2*)(feath + n * BN + 4 * lane) = pk;
            if ((lane & 15) == 0) {
                el[2 * n + (lane >> 4)] = ep;
                er[2 * n + (lane >> 4)] = rp;
            }
        }
    }
}

// ---------------- plain bf16 GEMM for BN=64 outputs (e2d, d2c) ----------------
template <int K, int BN, bool HAS_A2, bool GUARD>
__global__ __launch_bounds__(256) void gemm_bf16_kernel(
    const float* __restrict__ A, const float* __restrict__ A2, float scaleA,
    const float* __restrict__ W, float* __restrict__ outF)
{
    constexpr int BM = 128, KB = 32;
    constexpr int ASTR = KB + 8;
    constexpr int WSTR = BN + 8;
    constexpr int WYC = 4, WXC = 2;
    constexpr int WM = BM / WYC;    // 32
    constexpr int WN = BN / WXC;    // 32
    constexpr int AR = WM / 16;     // 2
    constexpr int AC = WN / 16;     // 2

    constexpr int AS_ELEMS = BM * ASTR;
    constexpr int WS_ELEMS = KB * WSTR;
    constexpr int MAIN_BYTES  = (2 * AS_ELEMS + 2 * WS_ELEMS) * 2;
    constexpr int STAGE_BYTES = GUARD ? BM * BN * 4 : 0;
    constexpr int SM_BYTES    = MAIN_BYTES > STAGE_BYTES ? MAIN_BYTES : STAGE_BYTES;

    __shared__ __align__(32) char sraw[SM_BYTES];
    bf16* AsH = (bf16*)sraw;
    bf16* AsL = AsH + AS_ELEMS;
    bf16* WsH = AsL + AS_ELEMS;
    bf16* WsL = WsH + WS_ELEMS;

    int tid = threadIdx.x;
    int wid = tid >> 5;
    int wy = wid / WXC;
    int wx = wid % WXC;
    long n0 = (long)blockIdx.x * BM;

    wmma::fragment<wmma::accumulator, 16, 16, 16, float> acc[AR][AC];
#pragma unroll
    for (int r = 0; r < AR; r++)
#pragma unroll
        for (int c = 0; c < AC; c++)
            wmma::fill_fragment(acc[r][c], 0.0f);

    for (int kb = 0; kb < K; kb += KB) {
#pragma unroll
        for (int it = 0; it < 4; it++) {
            int f4  = tid + it * 256;
            int row = f4 >> 3;
            int c4  = f4 & 7;
            long n  = n0 + row;
            float4 v = make_float4(0.f, 0.f, 0.f, 0.f);
            if (n < NN) {
                v = *(const float4*)(A + n * K + kb + 4 * c4);
                if (HAS_A2) {
                    float4 v2 = *(const float4*)(A2 + n * K + kb + 4 * c4);
                    v.x += v2.x; v.y += v2.y; v.z += v2.z; v.w += v2.w;
                }
                v.x *= scaleA; v.y *= scaleA; v.z *= scaleA; v.w *= scaleA;
            }
            bf16 h0, l0, h1, l1, h2, l2, h3, l3;
            split_bf16(v.x, h0, l0);
            split_bf16(v.y, h1, l1);
            split_bf16(v.z, h2, l2);
            split_bf16(v.w, h3, l3);
            int off = row * ASTR + 4 * c4;
            __nv_bfloat162 p;
            p.x = h0; p.y = h1; *(__nv_bfloat162*)&AsH[off]     = p;
            p.x = h2; p.y = h3; *(__nv_bfloat162*)&AsH[off + 2] = p;
            p.x = l0; p.y = l1; *(__nv_bfloat162*)&AsL[off]     = p;
            p.x = l2; p.y = l3; *(__nv_bfloat162*)&AsL[off + 2] = p;
        }
#pragma unroll
        for (int it = 0; it < KB * (BN / 4) / 256; it++) {
            int f4  = tid + it * 256;
            int row = f4 / (BN / 4);
            int c4  = f4 % (BN / 4);
            float4 v = *(const float4*)(W + (long)(kb + row) * BN + 4 * c4);
            bf16 h0, l0, h1, l1, h2, l2, h3, l3;
            split_bf16(v.x, h0, l0);
            split_bf16(v.y, h1, l1);
            split_bf16(v.z, h2, l2);
            split_bf16(v.w, h3, l3);
            int off = row * WSTR + 4 * c4;
            __nv_bfloat162 p;
            p.x = h0; p.y = h1; *(__nv_bfloat162*)&WsH[off]     = p;
            p.x = h2; p.y = h3; *(__nv_bfloat162*)&WsH[off + 2] = p;
            p.x = l0; p.y = l1; *(__nv_bfloat162*)&WsL[off]     = p;
            p.x = l2; p.y = l3; *(__nv_bfloat162*)&WsL[off + 2] = p;
        }
        __syncthreads();

#pragma unroll
        for (int ks = 0; ks < 2; ks++) {
            wmma::fragment<wmma::matrix_b, 16, 16, 16, bf16, wmma::row_major> bH[AC], bL[AC];
#pragma unroll
            for (int c = 0; c < AC; c++) {
                wmma::load_matrix_sync(bH[c], WsH + (ks * 16) * WSTR + wx * WN + c * 16, WSTR);
                wmma::load_matrix_sync(bL[c], WsL + (ks * 16) * WSTR + wx * WN + c * 16, WSTR);
            }
#pragma unroll
            for (int r = 0; r < AR; r++) {
                wmma::fragment<wmma::matrix_a, 16, 16, 16, bf16, wmma::row_major> aH, aL;
                wmma::load_matrix_sync(aH, AsH + (wy * WM + r * 16) * ASTR + ks * 16, ASTR);
                wmma::load_matrix_sync(aL, AsL + (wy * WM + r * 16) * ASTR + ks * 16, ASTR);
#pragma unroll
                for (int c = 0; c < AC; c++) {
                    wmma::mma_sync(acc[r][c], aH, bH[c], acc[r][c]);
                    wmma::mma_sync(acc[r][c], aH, bL[c], acc[r][c]);
                    wmma::mma_sync(acc[r][c], aL, bH[c], acc[r][c]);
                }
            }
        }
        __syncthreads();
    }

    if (!GUARD) {
#pragma unroll
        for (int r = 0; r < AR; r++)
#pragma unroll
            for (int c = 0; c < AC; c++)
                wmma::store_matrix_sync(outF + (n0 + wy * WM + r * 16) * BN + wx * WN + c * 16,
                                        acc[r][c], BN, wmma::mem_row_major);
    } else {
        float* stage = (float*)sraw;
#pragma unroll
        for (int r = 0; r < AR; r++)
#pragma unroll
            for (int c = 0; c < AC; c++)
                wmma::store_matrix_sync(stage + (wy * WM + r * 16) * BN + wx * WN + c * 16,
                                        acc[r][c], BN, wmma::mem_row_major);
        __syncthreads();
#pragma unroll
        for (int it = 0; it < BM * (BN / 4) / 256; it++) {
            int f4  = tid + it * 256;
            int row = f4 / (BN / 4);
            int c4  = f4 % (BN / 4);
            long n  = n0 + row;
            if (n < NN)
                *(float4*)(outF + n * BN + 4 * c4) = *(float4*)(stage + row * BN + 4 * c4);
        }
    }
}

// ---------------- attention: warp per node; edge softmax + fp16 gather + bias + ELU ----------------
__global__ __launch_bounds__(256) void attn_kernel(
    const __half* __restrict__ feath, const float* __restrict__ el, const float* __restrict__ er,
    const float* __restrict__ bias, float* __restrict__ out, int accumulate)
{
    int warp = (blockIdx.x * blockDim.x + threadIdx.x) >> 5;
    if (warp >= NN) return;
    int lane = threadIdx.x & 31;

    int s = g_ptr[warp], e = g_ptr[warp + 1];
    float er0 = er[2 * warp], er1 = er[2 * warp + 1];

    // pass 1: online softmax stats (fp32 logits)
    float m0 = -1e30f, m1 = -1e30f, s0 = 0.f, s1 = 0.f;
    for (int i = s + lane; i < e; i += 32) {
        int sv = g_csrc[i];
        float2 ev = *(const float2*)(el + 2 * sv);
        float e0 = ev.x + er0; e0 = (e0 > 0.f) ? e0 : 0.2f * e0;
        float e1 = ev.y + er1; e1 = (e1 > 0.f) ? e1 : 0.2f * e1;
        float nm0 = fmaxf(m0, e0);
        s0 = s0 * __expf(m0 - nm0) + __expf(e0 - nm0);
        m0 = nm0;
        float nm1 = fmaxf(m1, e1);
        s1 = s1 * __expf(m1 - nm1) + __expf(e1 - nm1);
        m1 = nm1;
    }
#pragma unroll
    for (int off = 16; off; off >>= 1) {
        float om0 = __shfl_down_sync(0xffffffffu, m0, off);
        float os0 = __shfl_down_sync(0xffffffffu, s0, off);
        float nm0 = fmaxf(m0, om0);
        s0 = s0 * __expf(m0 - nm0) + os0 * __expf(om0 - nm0);
        m0 = nm0;
        float om1 = __shfl_down_sync(0xffffffffu, m1, off);
        float os1 = __shfl_down_sync(0xffffffffu, s1, off);
        float nm1 = fmaxf(m1, om1);
        s1 = s1 * __expf(m1 - nm1) + os1 * __expf(om1 - nm1);
        m1 = nm1;
    }
    m0 = __shfl_sync(0xffffffffu, m0, 0);
    s0 = __shfl_sync(0xffffffffu, s0, 0);
    m1 = __shfl_sync(0xffffffffu, m1, 0);
    s1 = __shfl_sync(0xffffffffu, s1, 0);
    float inv0 = 1.f / s0, inv1 = 1.f / s1;

    // pass 2: weighted gather from fp16 shadow (256B/edge)
    int colbase = 4 * lane;
    const bool head0 = (colbase < 64);
    const __half* feathc = feath + colbase;
    float4 acc = make_float4(0.f, 0.f, 0.f, 0.f);
    for (int base = s; base < e; base += 32) {
        int i = base + lane;
        float a0 = 0.f, a1 = 0.f;
        int sv = 0;
        if (i < e) {
            sv = g_csrc[i];
            float2 ev = *(const float2*)(el + 2 * sv);
            float e0 = ev.x + er0; e0 = (e0 > 0.f) ? e0 : 0.2f * e0;
            float e1 = ev.y + er1; e1 = (e1 > 0.f) ? e1 : 0.2f * e1;
            a0 = __expf(e0 - m0) * inv0;
            a1 = __expf(e1 - m1) * inv1;
        }
        int cnt = e - base; if (cnt > 32) cnt = 32;
        for (int j = 0; j < cnt; j++) {
            int sj = __shfl_sync(0xffffffffu, sv, j);
            float q0 = __shfl_sync(0xffffffffu, a0, j);
            float q1 = __shfl_sync(0xffffffffu, a1, j);
            float wj = head0 ? q0 : q1;
            uint2 hraw = *(const uint2*)(feathc + (long)sj * HDDIM);
            float2 f01 = __half22float2(*(__half2*)&hraw.x);
            float2 f23 = __half22float2(*(__half2*)&hraw.y);
            acc.x += wj * f01.x;
            acc.y += wj * f01.y;
            acc.z += wj * f23.x;
            acc.w += wj * f23.y;
        }
    }

    float4 bv = *(const float4*)(bias + colbase);
    float4 v;
    v.x = acc.x + bv.x; v.x = (v.x > 0.f) ? v.x : expm1f(v.x);
    v.y = acc.y + bv.y; v.y = (v.y > 0.f) ? v.y : expm1f(v.y);
    v.z = acc.z + bv.z; v.z = (v.z > 0.f) ? v.z : expm1f(v.z);
    v.w = acc.w + bv.w; v.w = (v.w > 0.f) ? v.w : expm1f(v.w);

    float* o = out + (long)warp * HDDIM + colbase;
    if (accumulate) {
        float4 p = *(const float4*)o;
        v.x += p.x; v.y += p.y; v.z += p.z; v.w += p.w;
    }
    *(float4*)o = v;
}

// ---------------- host ----------------
extern "C" void kernel_launch(void* const* d_in, const int* in_sizes, int n_in,
                              void* d_out, int out_size)
{
    const float* x        = (const float*)d_in[0];
    const int*   src      = (const int*)d_in[1];
    const int*   dst      = (const int*)d_in[2];
    const int*   encm     = (const int*)d_in[3];
    const int*   remask   = (const int*)d_in[4];
    const float* enc_fc0  = (const float*)d_in[5];
    const float* enc_al0  = (const float*)d_in[6];
    const float* enc_ar0  = (const float*)d_in[7];
    const float* enc_b0   = (const float*)d_in[8];
    const float* enc_fc1  = (const float*)d_in[9];
    const float* enc_al1  = (const float*)d_in[10];
    const float* enc_ar1  = (const float*)d_in[11];
    const float* enc_b1   = (const float*)d_in[12];
    const float* dec_fc0  = (const float*)d_in[13];
    const float* dec_al0  = (const float*)d_in[14];
    const float* dec_ar0  = (const float*)d_in[15];
    const float* dec_b0   = (const float*)d_in[16];
    const float* dec_fc1  = (const float*)d_in[17];
    const float* dec_al1  = (const float*)d_in[18];
    const float* dec_ar1  = (const float*)d_in[19];
    const float* dec_b1   = (const float*)d_in[20];
    const float* dec_tok  = (const float*)d_in[22];
    const float* W_e2d    = (const float*)d_in[23];
    const float* W_d2c    = (const float*)d_in[24];
    const float* enc_tok  = (const float*)d_in[21];
    float* out = (float*)d_out;

    int encCnt    = in_sizes[3];
    int remaskCnt = in_sizes[4] / 3;

    void *p_feat, *p_feath, *p_el, *p_er, *p_h0, *p_h1, *p_rep0, *p_r0, *p_acc;
    cudaGetSymbolAddress(&p_feat,  g_feat);
    cudaGetSymbolAddress(&p_feath, g_feath);
    cudaGetSymbolAddress(&p_el,    g_el);
    cudaGetSymbolAddress(&p_er,    g_er);
    cudaGetSymbolAddress(&p_h0,    g_h0);
    cudaGetSymbolAddress(&p_h1,    g_h1);
    cudaGetSymbolAddress(&p_rep0,  g_rep0);
    cudaGetSymbolAddress(&p_r0,    g_r0);
    cudaGetSymbolAddress(&p_acc,   g_accb);

    float*  feat  = (float*)p_feat;
    __half* feath = (__half*)p_feath;
    float*  el    = (float*)p_el;
    float*  er    = (float*)p_er;
    float*  h0    = (float*)p_h0;
    float*  h1    = (float*)p_h1;
    float*  rep0  = (float*)p_rep0;
    float*  r0    = (float*)p_r0;
    float*  accb  = (float*)p_acc;

    const int EB  = (EE + 255) / 256;
    const int GTC = NNPAD / 128;
    const int AB  = (NN + 7) / 8;
    const int DSM = 65536;   // dynamic smem for gemm_elr (stage 128*128*4 = 64KB > mainloop 37.9KB)

    cudaFuncSetAttribute(gemm_elr_kernel<INDIM, true>,
                         cudaFuncAttributeMaxDynamicSharedMemorySize, DSM);
    cudaFuncSetAttribute(gemm_elr_kernel<HDDIM, false>,
                         cudaFuncAttributeMaxDynamicSharedMemorySize, DSM);

    // ---- CSR + flags (g_cnt/g_rflag are zero here: static init / previous call's cleanup) ----
    prep_kernel<<<EB, 256>>>(dst, encm, encCnt, remask, remaskCnt);   // kernel 2 (poison=1)
    scan_kernel<<<1, 1024>>>();                                       // 3
    scatter_kernel<<<EB, 256>>>(src, dst);                            // 4

    // ---- encoder layer 0 (reads x with enc-token substitution, bit 3) ----
    gemm_elr_kernel<INDIM, true><<<GTC, 256, DSM>>>(
        x, enc_fc0, enc_al0, enc_ar0, enc_tok, 3, feat, el, er, feath);   // 5
    attn_kernel<<<AB, 256>>>(feath, el, er, enc_b0, h0, 0);               // 6 <- ncu -s 5 -c 1

    // ---- encoder layer 1 ----
    gemm_elr_kernel<HDDIM, false><<<GTC, 256, DSM>>>(
        h0, enc_fc1, enc_al1, enc_ar1, nullptr, 0, feat, el, er, feath);
    attn_kernel<<<AB, 256>>>(feath, el, er, enc_b1, h1, 0);

    // ---- Es = 0.5*(h0+h1); origin_rep = Es @ W_e2d ----
    gemm_bf16_kernel<HDDIM, INDIM, true, false><<<GTC, 256>>>(h0, h1, 0.5f, W_e2d, rep0);

    // ---- decoder x3, accumulate r1 into accb ----
    cudaMemsetAsync(p_acc, 0, (size_t)NN * HDDIM * sizeof(float));
    for (int i = 0; i < 3; i++) {
        gemm_elr_kernel<INDIM, true><<<GTC, 256, DSM>>>(
            rep0, dec_fc0, dec_al0, dec_ar0, dec_tok, i, feat, el, er, feath);
        attn_kernel<<<AB, 256>>>(feath, el, er, dec_b0, r0, 0);

        gemm_elr_kernel<HDDIM, false><<<GTC, 256, DSM>>>(
            r0, dec_fc1, dec_al1, dec_ar1, nullptr, 0, feat, el, er, feath);
        attn_kernel<<<AB, 256>>>(feath, el, er, dec_b1, accb, 1);
    }

    // ---- out = (accb/3) @ W_d2c ----
    gemm_bf16_kernel<HDDIM, INDIM, false, true><<<GTC, 256>>>(accb, nullptr, 1.f / 3.f, W_d2c, out);

    // ---- restore g_cnt/g_rflag to zero for the next call ----
    cleanup_kernel<<<(NN + 255) / 256, 256>>>();
}

// round 17
// speedup vs baseline: 1.1198x; 1.1198x over previous
#include <cuda_runtime.h>
#include <cuda_bf16.h>
#include <cuda_fp16.h>
#include <cstdint>
#include <mma.h>

using namespace nvcuda;
typedef __nv_bfloat16 bf16;

#define NN 100000
#define NNPAD 100096   // 782 * 128
#define EE 1600000
#define INDIM 64
#define HDDIM 128

// ---------------- scratch (static device globals; no allocation) ----------------
__device__ float g_feat [NNPAD * HDDIM];
__device__ __half g_feath[NN * HDDIM];   // fp16 shadow of feat for the gather pass
__device__ float g_el   [NN * 2];
__device__ float g_er   [NN * 2];
__device__ float g_h0   [NN * HDDIM];
__device__ float g_h1   [NN * HDDIM];
__device__ float g_rep0 [NNPAD * INDIM];
__device__ float g_r0   [NN * HDDIM];
__device__ float g_accb [NN * HDDIM];
__device__ int   g_ptr  [NN + 1];
__device__ int   g_cnt  [NN];      // zero at load; every call leaves it zero
__device__ int   g_csrc [EE];
__device__ int   g_rflag[NN];      // bits 0-2: decoder iter remask; bit 3: encoder mask. zero at load & after each call.

// ---------------- prep: edge histogram + all mask flags in one launch ----------------
__global__ void prep_kernel(const int* __restrict__ dst,
                            const int* __restrict__ encm, int encCnt,
                            const int* __restrict__ remask, int remaskCnt) {
    int i = blockIdx.x * blockDim.x + threadIdx.x;
    if (i < EE) atomicAdd(&g_cnt[dst[i]], 1);
    if (i < encCnt) atomicOr(&g_rflag[encm[i]], 8);
    if (i < 3 * remaskCnt) atomicOr(&g_rflag[remask[i]], 1 << (i / remaskCnt));
}

// exclusive-scan degrees into g_ptr, re-zero g_cnt for scatter
__global__ void scan_kernel() {
    const int T = 1024;
    const int CH = (NN + T - 1) / T;
    __shared__ int ss[T];
    int t = threadIdx.x;
    int lo = t * CH;
    int hi = lo + CH; if (hi > NN) hi = NN;
    int s = 0;
    for (int i = lo; i < hi; i++) s += g_cnt[i];
    ss[t] = s;
    __syncthreads();
    for (int off = 1; off < T; off <<= 1) {
        int v = (t >= off) ? ss[t - off] : 0;
        __syncthreads();
        ss[t] += v;
        __syncthreads();
    }
    int run = (t == 0) ? 0 : ss[t - 1];
    for (int i = lo; i < hi; i++) { g_ptr[i] = run; run += g_cnt[i]; g_cnt[i] = 0; }
    if (t == 0) g_ptr[NN] = ss[T - 1];
}

__global__ void scatter_kernel(const int* __restrict__ src, const int* __restrict__ dst) {
    int i = blockIdx.x * blockDim.x + threadIdx.x;
    if (i < EE) {
        int d = dst[i];
        int off = atomicAdd(&g_cnt[d], 1);
        g_csrc[g_ptr[d] + off] = src[i];
    }
}

// tail: restore g_cnt and g_rflag to zero for the next call
__global__ void cleanup_kernel() {
    int i = blockIdx.x * blockDim.x + threadIdx.x;
    if (i < NN) { g_cnt[i] = 0; g_rflag[i] = 0; }
}

// ---------------- bf16 split helper: v = hi + lo + O(2^-18 v) ----------------
__device__ __forceinline__ void split_bf16(float v, bf16& h, bf16& l) {
    h = __float2bfloat16_rn(v);
    l = __float2bfloat16_rn(v - __bfloat162float(h));
}

// ---------------- fused GEMM + elr: feat = A@W (bf16 3-term), el/er logits, fp16 shadow ----------------
// BN = 128 fixed. Optional per-row token substitution via g_rflag bit `iter`.
// Static smem only; epilogue stages 64 rows at a time so 2 CTAs/SM fit (regs capped via launch_bounds).
template <int K, bool REMASK>
__global__ __launch_bounds__(256, 2) void gemm_elr_kernel(
    const float* __restrict__ A, const float* __restrict__ W,
    const float* __restrict__ al, const float* __restrict__ ar,
    const float* __restrict__ token, int iter,
    float* __restrict__ outF, float* __restrict__ el, float* __restrict__ er,
    __half* __restrict__ feath)
{
    constexpr int BM = 128, BN = 128, KB = 32;
    constexpr int ASTR = KB + 8;    // 40
    constexpr int WSTR = BN + 8;    // 136
    constexpr int WM = 64, WN = 32, AR = 4, AC = 2;
    constexpr int AS_ELEMS = BM * ASTR;
    constexpr int WS_ELEMS = KB * WSTR;
    constexpr int MAIN_BYTES  = (2 * AS_ELEMS + 2 * WS_ELEMS) * 2;   // 37888
    constexpr int STAGE_BYTES = 64 * BN * 4;                          // 32768 (half stage)
    constexpr int SM_BYTES    = MAIN_BYTES > STAGE_BYTES ? MAIN_BYTES : STAGE_BYTES;

    __shared__ __align__(32) char sraw[SM_BYTES];
    bf16* AsH = (bf16*)sraw;
    bf16* AsL = AsH + AS_ELEMS;
    bf16* WsH = AsL + AS_ELEMS;
    bf16* WsL = WsH + WS_ELEMS;

    int tid = threadIdx.x;
    int wid = tid >> 5;
    int lane = tid & 31;
    int wy = wid >> 2;
    int wx = wid & 3;
    long n0 = (long)blockIdx.x * BM;

    wmma::fragment<wmma::accumulator, 16, 16, 16, float> acc[AR][AC];
#pragma unroll
    for (int r = 0; r < AR; r++)
#pragma unroll
        for (int c = 0; c < AC; c++)
            wmma::fill_fragment(acc[r][c], 0.0f);

    for (int kb = 0; kb < K; kb += KB) {
#pragma unroll
        for (int it = 0; it < 4; it++) {
            int f4  = tid + it * 256;
            int row = f4 >> 3;
            int c4  = f4 & 7;
            long n  = n0 + row;
            float4 v = make_float4(0.f, 0.f, 0.f, 0.f);
            if (n < NN) {
                if (REMASK && ((g_rflag[n] >> iter) & 1)) {
                    v = *(const float4*)(token + kb + 4 * c4);
                } else {
                    v = *(const float4*)(A + n * K + kb + 4 * c4);
                }
            }
            bf16 h0, l0, h1, l1, h2, l2, h3, l3;
            split_bf16(v.x, h0, l0);
            split_bf16(v.y, h1, l1);
            split_bf16(v.z, h2, l2);
            split_bf16(v.w, h3, l3);
            int off = row * ASTR + 4 * c4;
            __nv_bfloat162 p;
            p.x = h0; p.y = h1; *(__nv_bfloat162*)&AsH[off]     = p;
            p.x = h2; p.y = h3; *(__nv_bfloat162*)&AsH[off + 2] = p;
            p.x = l0; p.y = l1; *(__nv_bfloat162*)&AsL[off]     = p;
            p.x = l2; p.y = l3; *(__nv_bfloat162*)&AsL[off + 2] = p;
        }
#pragma unroll
        for (int it = 0; it < 4; it++) {
            int f4  = tid + it * 256;
            int row = f4 >> 5;
            int c4  = f4 & 31;
            float4 v = *(const float4*)(W + (long)(kb + row) * BN + 4 * c4);
            bf16 h0, l0, h1, l1, h2, l2, h3, l3;
            split_bf16(v.x, h0, l0);
            split_bf16(v.y, h1, l1);
            split_bf16(v.z, h2, l2);
            split_bf16(v.w, h3, l3);
            int off = row * WSTR + 4 * c4;
            __nv_bfloat162 p;
            p.x = h0; p.y = h1; *(__nv_bfloat162*)&WsH[off]     = p;
            p.x = h2; p.y = h3; *(__nv_bfloat162*)&WsH[off + 2] = p;
            p.x = l0; p.y = l1; *(__nv_bfloat162*)&WsL[off]     = p;
            p.x = l2; p.y = l3; *(__nv_bfloat162*)&WsL[off + 2] = p;
        }
        __syncthreads();

#pragma unroll
        for (int ks = 0; ks < 2; ks++) {
            wmma::fragment<wmma::matrix_b, 16, 16, 16, bf16, wmma::row_major> bH[AC], bL[AC];
#pragma unroll
            for (int c = 0; c < AC; c++) {
                wmma::load_matrix_sync(bH[c], WsH + (ks * 16) * WSTR + wx * WN + c * 16, WSTR);
                wmma::load_matrix_sync(bL[c], WsL + (ks * 16) * WSTR + wx * WN + c * 16, WSTR);
            }
#pragma unroll
            for (int r = 0; r < AR; r++) {
                wmma::fragment<wmma::matrix_a, 16, 16, 16, bf16, wmma::row_major> aH, aL;
                wmma::load_matrix_sync(aH, AsH + (wy * WM + r * 16) * ASTR + ks * 16, ASTR);
                wmma::load_matrix_sync(aL, AsL + (wy * WM + r * 16) * ASTR + ks * 16, ASTR);
#pragma unroll
                for (int c = 0; c < AC; c++) {
                    wmma::mma_sync(acc[r][c], aH, bH[c], acc[r][c]);
                    wmma::mma_sync(acc[r][c], aH, bL[c], acc[r][c]);
                    wmma::mma_sync(acc[r][c], aL, bH[c], acc[r][c]);
                }
            }
        }
        __syncthreads();
    }

    // ---- fused epilogue in two 64-row halves (stage reuses mainloop smem) ----
    float* stage = (float*)sraw;
    float4 a4 = *(const float4*)(al + 4 * lane);
    float4 r4 = *(const float4*)(ar + 4 * lane);

#pragma unroll
    for (int h = 0; h < 2; h++) {
        if (wy == h) {
#pragma unroll
            for (int r = 0; r < AR; r++)
#pragma unroll
                for (int c = 0; c < AC; c++)
                    wmma::store_matrix_sync(stage + (r * 16) * BN + wx * WN + c * 16,
                                            acc[r][c], BN, wmma::mem_row_major);
        }
        __syncthreads();
        // 8 warps emit 8 rows each of this 64-row half
#pragma unroll
        for (int rr = 0; rr < 8; rr++) {
            int rowl = wid * 8 + rr;            // 0..63
            long n = n0 + h * 64 + rowl;
            float4 f = *(float4*)(stage + rowl * BN + 4 * lane);
            *(float4*)(outF + n * BN + 4 * lane) = f;      // feat padded to NNPAD: unguarded
            float ep = f.x * a4.x + f.y * a4.y + f.z * a4.z + f.w * a4.w;
            float rp = f.x * r4.x + f.y * r4.y + f.z * r4.z + f.w * r4.w;
#pragma unroll
            for (int off = 8; off; off >>= 1) {
                ep += __shfl_down_sync(0xffffffffu, ep, off, 16);
                rp += __shfl_down_sync(0xffffffffu, rp, off, 16);
            }
            if (n < NN) {
                __half2 hlo = __floats2half2_rn(f.x, f.y);
                __half2 hhi = __floats2half2_rn(f.z, f.w);
                uint2 pk;
                pk.x = *(unsigned int*)&hlo;
                pk.y = *(unsigned int*)&hhi;
                *(uint2*)(feath + n * BN + 4 * lane) = pk;
                if ((lane & 15) == 0) {
                    el[2 * n + (lane >> 4)] = ep;
                    er[2 * n + (lane >> 4)] = rp;
                }
            }
        }
        __syncthreads();
    }
}

// ---------------- plain bf16 GEMM for BN=64 outputs (e2d, d2c) ----------------
template <int K, int BN, bool HAS_A2, bool GUARD>
__global__ __launch_bounds__(256, 2) void gemm_bf16_kernel(
    const float* __restrict__ A, const float* __restrict__ A2, float scaleA,
    const float* __restrict__ W, float* __restrict__ outF)
{
    constexpr int BM = 128, KB = 32;
    constexpr int ASTR = KB + 8;
    constexpr int WSTR = BN + 8;
    constexpr int WYC = 4, WXC = 2;
    constexpr int WM = BM / WYC;    // 32
    constexpr int WN = BN / WXC;    // 32
    constexpr int AR = WM / 16;     // 2
    constexpr int AC = WN / 16;     // 2

    constexpr int AS_ELEMS = BM * ASTR;
    constexpr int WS_ELEMS = KB * WSTR;
    constexpr int MAIN_BYTES  = (2 * AS_ELEMS + 2 * WS_ELEMS) * 2;
    constexpr int STAGE_BYTES = GUARD ? BM * BN * 4 : 0;
    constexpr int SM_BYTES    = MAIN_BYTES > STAGE_BYTES ? MAIN_BYTES : STAGE_BYTES;

    __shared__ __align__(32) char sraw[SM_BYTES];
    bf16* AsH = (bf16*)sraw;
    bf16* AsL = AsH + AS_ELEMS;
    bf16* WsH = AsL + AS_ELEMS;
    bf16* WsL = WsH + WS_ELEMS;

    int tid = threadIdx.x;
    int wid = tid >> 5;
    int wy = wid / WXC;
    int wx = wid % WXC;
    long n0 = (long)blockIdx.x * BM;

    wmma::fragment<wmma::accumulator, 16, 16, 16, float> acc[AR][AC];
#pragma unroll
    for (int r = 0; r < AR; r++)
#pragma unroll
        for (int c = 0; c < AC; c++)
            wmma::fill_fragment(acc[r][c], 0.0f);

    for (int kb = 0; kb < K; kb += KB) {
#pragma unroll
        for (int it = 0; it < 4; it++) {
            int f4  = tid + it * 256;
            int row = f4 >> 3;
            int c4  = f4 & 7;
            long n  = n0 + row;
            float4 v = make_float4(0.f, 0.f, 0.f, 0.f);
            if (n < NN) {
                v = *(const float4*)(A + n * K + kb + 4 * c4);
                if (HAS_A2) {
                    float4 v2 = *(const float4*)(A2 + n * K + kb + 4 * c4);
                    v.x += v2.x; v.y += v2.y; v.z += v2.z; v.w += v2.w;
                }
                v.x *= scaleA; v.y *= scaleA; v.z *= scaleA; v.w *= scaleA;
            }
            bf16 h0, l0, h1, l1, h2, l2, h3, l3;
            split_bf16(v.x, h0, l0);
            split_bf16(v.y, h1, l1);
            split_bf16(v.z, h2, l2);
            split_bf16(v.w, h3, l3);
            int off = row * ASTR + 4 * c4;
            __nv_bfloat162 p;
            p.x = h0; p.y = h1; *(__nv_bfloat162*)&AsH[off]     = p;
            p.x = h2; p.y = h3; *(__nv_bfloat162*)&AsH[off + 2] = p;
            p.x = l0; p.y = l1; *(__nv_bfloat162*)&AsL[off]     = p;
            p.x = l2; p.y = l3; *(__nv_bfloat162*)&AsL[off + 2] = p;
        }
#pragma unroll
        for (int it = 0; it < KB * (BN / 4) / 256; it++) {
            int f4  = tid + it * 256;
            int row = f4 / (BN / 4);
            int c4  = f4 % (BN / 4);
            float4 v = *(const float4*)(W + (long)(kb + row) * BN + 4 * c4);
            bf16 h0, l0, h1, l1, h2, l2, h3, l3;
            split_bf16(v.x, h0, l0);
            split_bf16(v.y, h1, l1);
            split_bf16(v.z, h2, l2);
            split_bf16(v.w, h3, l3);
            int off = row * WSTR + 4 * c4;
            __nv_bfloat162 p;
            p.x = h0; p.y = h1; *(__nv_bfloat162*)&WsH[off]     = p;
            p.x = h2; p.y = h3; *(__nv_bfloat162*)&WsH[off + 2] = p;
            p.x = l0; p.y = l1; *(__nv_bfloat162*)&WsL[off]     = p;
            p.x = l2; p.y = l3; *(__nv_bfloat162*)&WsL[off + 2] = p;
        }
        __syncthreads();

#pragma unroll
        for (int ks = 0; ks < 2; ks++) {
            wmma::fragment<wmma::matrix_b, 16, 16, 16, bf16, wmma::row_major> bH[AC], bL[AC];
#pragma unroll
            for (int c = 0; c < AC; c++) {
                wmma::load_matrix_sync(bH[c], WsH + (ks * 16) * WSTR + wx * WN + c * 16, WSTR);
                wmma::load_matrix_sync(bL[c], WsL + (ks * 16) * WSTR + wx * WN + c * 16, WSTR);
            }
#pragma unroll
            for (int r = 0; r < AR; r++) {
                wmma::fragment<wmma::matrix_a, 16, 16, 16, bf16, wmma::row_major> aH, aL;
                wmma::load_matrix_sync(aH, AsH + (wy * WM + r * 16) * ASTR + ks * 16, ASTR);
                wmma::load_matrix_sync(aL, AsL + (wy * WM + r * 16) * ASTR + ks * 16, ASTR);
#pragma unroll
                for (int c = 0; c < AC; c++) {
                    wmma::mma_sync(acc[r][c], aH, bH[c], acc[r][c]);
                    wmma::mma_sync(acc[r][c], aH, bL[c], acc[r][c]);
                    wmma::mma_sync(acc[r][c], aL, bH[c], acc[r][c]);
                }
            }
        }
        __syncthreads();
    }

    if (!GUARD) {
#pragma unroll
        for (int r = 0; r < AR; r++)
#pragma unroll
            for (int c = 0; c < AC; c++)
                wmma::store_matrix_sync(outF + (n0 + wy * WM + r * 16) * BN + wx * WN + c * 16,
                                        acc[r][c], BN, wmma::mem_row_major);
    } else {
        float* stage = (float*)sraw;
#pragma unroll
        for (int r = 0; r < AR; r++)
#pragma unroll
            for (int c = 0; c < AC; c++)
                wmma::store_matrix_sync(stage + (wy * WM + r * 16) * BN + wx * WN + c * 16,
                                        acc[r][c], BN, wmma::mem_row_major);
        __syncthreads();
#pragma unroll
        for (int it = 0; it < BM * (BN / 4) / 256; it++) {
            int f4  = tid + it * 256;
            int row = f4 / (BN / 4);
            int c4  = f4 % (BN / 4);
            long n  = n0 + row;
            if (n < NN)
                *(float4*)(outF + n * BN + 4 * c4) = *(float4*)(stage + row * BN + 4 * c4);
        }
    }
}

// ---------------- attention: warp per node; edge softmax + fp16 gather + bias + ELU ----------------
__global__ __launch_bounds__(256) void attn_kernel(
    const __half* __restrict__ feath, const float* __restrict__ el, const float* __restrict__ er,
    const float* __restrict__ bias, float* __restrict__ out, int accumulate)
{
    int warp = (blockIdx.x * blockDim.x + threadIdx.x) >> 5;
    if (warp >= NN) return;
    int lane = threadIdx.x & 31;

    int s = g_ptr[warp], e = g_ptr[warp + 1];
    float er0 = er[2 * warp], er1 = er[2 * warp + 1];

    // pass 1: online softmax stats (fp32 logits)
    float m0 = -1e30f, m1 = -1e30f, s0 = 0.f, s1 = 0.f;
    for (int i = s + lane; i < e; i += 32) {
        int sv = g_csrc[i];
        float2 ev = *(const float2*)(el + 2 * sv);
        float e0 = ev.x + er0; e0 = (e0 > 0.f) ? e0 : 0.2f * e0;
        float e1 = ev.y + er1; e1 = (e1 > 0.f) ? e1 : 0.2f * e1;
        float nm0 = fmaxf(m0, e0);
        s0 = s0 * __expf(m0 - nm0) + __expf(e0 - nm0);
        m0 = nm0;
        float nm1 = fmaxf(m1, e1);
        s1 = s1 * __expf(m1 - nm1) + __expf(e1 - nm1);
        m1 = nm1;
    }
#pragma unroll
    for (int off = 16; off; off >>= 1) {
        float om0 = __shfl_down_sync(0xffffffffu, m0, off);
        float os0 = __shfl_down_sync(0xffffffffu, s0, off);
        float nm0 = fmaxf(m0, om0);
        s0 = s0 * __expf(m0 - nm0) + os0 * __expf(om0 - nm0);
        m0 = nm0;
        float om1 = __shfl_down_sync(0xffffffffu, m1, off);
        float os1 = __shfl_down_sync(0xffffffffu, s1, off);
        float nm1 = fmaxf(m1, om1);
        s1 = s1 * __expf(m1 - nm1) + os1 * __expf(om1 - nm1);
        m1 = nm1;
    }
    m0 = __shfl_sync(0xffffffffu, m0, 0);
    s0 = __shfl_sync(0xffffffffu, s0, 0);
    m1 = __shfl_sync(0xffffffffu, m1, 0);
    s1 = __shfl_sync(0xffffffffu, s1, 0);
    float inv0 = 1.f / s0, inv1 = 1.f / s1;

    // pass 2: weighted gather from fp16 shadow (256B/edge)
    int colbase = 4 * lane;
    const bool head0 = (colbase < 64);
    const __half* feathc = feath + colbase;
    float4 acc = make_float4(0.f, 0.f, 0.f, 0.f);
    for (int base = s; base < e; base += 32) {
        int i = base + lane;
        float a0 = 0.f, a1 = 0.f;
        int sv = 0;
        if (i < e) {
            sv = g_csrc[i];
            float2 ev = *(const float2*)(el + 2 * sv);
            float e0 = ev.x + er0; e0 = (e0 > 0.f) ? e0 : 0.2f * e0;
            float e1 = ev.y + er1; e1 = (e1 > 0.f) ? e1 : 0.2f * e1;
            a0 = __expf(e0 - m0) * inv0;
            a1 = __expf(e1 - m1) * inv1;
        }
        int cnt = e - base; if (cnt > 32) cnt = 32;
        for (int j = 0; j < cnt; j++) {
            int sj = __shfl_sync(0xffffffffu, sv, j);
            float q0 = __shfl_sync(0xffffffffu, a0, j);
            float q1 = __shfl_sync(0xffffffffu, a1, j);
            float wj = head0 ? q0 : q1;
            uint2 hraw = *(const uint2*)(feathc + (long)sj * HDDIM);
            float2 f01 = __half22float2(*(__half2*)&hraw.x);
            float2 f23 = __half22float2(*(__half2*)&hraw.y);
            acc.x += wj * f01.x;
            acc.y += wj * f01.y;
            acc.z += wj * f23.x;
            acc.w += wj * f23.y;
        }
    }

    float4 bv = *(const float4*)(bias + colbase);
    float4 v;
    v.x = acc.x + bv.x; v.x = (v.x > 0.f) ? v.x : expm1f(v.x);
    v.y = acc.y + bv.y; v.y = (v.y > 0.f) ? v.y : expm1f(v.y);
    v.z = acc.z + bv.z; v.z = (v.z > 0.f) ? v.z : expm1f(v.z);
    v.w = acc.w + bv.w; v.w = (v.w > 0.f) ? v.w : expm1f(v.w);

    float* o = out + (long)warp * HDDIM + colbase;
    if (accumulate) {
        float4 p = *(const float4*)o;
        v.x += p.x; v.y += p.y; v.z += p.z; v.w += p.w;
    }
    *(float4*)o = v;
}

// ---------------- host ----------------
extern "C" void kernel_launch(void* const* d_in, const int* in_sizes, int n_in,
                              void* d_out, int out_size)
{
    const float* x        = (const float*)d_in[0];
    const int*   src      = (const int*)d_in[1];
    const int*   dst      = (const int*)d_in[2];
    const int*   encm     = (const int*)d_in[3];
    const int*   remask   = (const int*)d_in[4];
    const float* enc_fc0  = (const float*)d_in[5];
    const float* enc_al0  = (const float*)d_in[6];
    const float* enc_ar0  = (const float*)d_in[7];
    const float* enc_b0   = (const float*)d_in[8];
    const float* enc_fc1  = (const float*)d_in[9];
    const float* enc_al1  = (const float*)d_in[10];
    const float* enc_ar1  = (const float*)d_in[11];
    const float* enc_b1   = (const float*)d_in[12];
    const float* dec_fc0  = (const float*)d_in[13];
    const float* dec_al0  = (const float*)d_in[14];
    const float* dec_ar0  = (const float*)d_in[15];
    const float* dec_b0   = (const float*)d_in[16];
    const float* dec_fc1  = (const float*)d_in[17];
    const float* dec_al1  = (const float*)d_in[18];
    const float* dec_ar1  = (const float*)d_in[19];
    const float* dec_b1   = (const float*)d_in[20];
    const float* enc_tok  = (const float*)d_in[21];
    const float* dec_tok  = (const float*)d_in[22];
    const float* W_e2d    = (const float*)d_in[23];
    const float* W_d2c    = (const float*)d_in[24];
    float* out = (float*)d_out;

    int encCnt    = in_sizes[3];
    int remaskCnt = in_sizes[4] / 3;

    void *p_feat, *p_feath, *p_el, *p_er, *p_h0, *p_h1, *p_rep0, *p_r0, *p_acc;
    cudaGetSymbolAddress(&p_feat,  g_feat);
    cudaGetSymbolAddress(&p_feath, g_feath);
    cudaGetSymbolAddress(&p_el,    g_el);
    cudaGetSymbolAddress(&p_er,    g_er);
    cudaGetSymbolAddress(&p_h0,    g_h0);
    cudaGetSymbolAddress(&p_h1,    g_h1);
    cudaGetSymbolAddress(&p_rep0,  g_rep0);
    cudaGetSymbolAddress(&p_r0,    g_r0);
    cudaGetSymbolAddress(&p_acc,   g_accb);

    float*  feat  = (float*)p_feat;
    __half* feath = (__half*)p_feath;
    float*  el    = (float*)p_el;
    float*  er    = (float*)p_er;
    float*  h0    = (float*)p_h0;
    float*  h1    = (float*)p_h1;
    float*  rep0  = (float*)p_rep0;
    float*  r0    = (float*)p_r0;
    float*  accb  = (float*)p_acc;

    const int EB  = (EE + 255) / 256;
    const int GTC = NNPAD / 128;
    const int AB  = (NN + 7) / 8;

    // ---- CSR + flags (g_cnt/g_rflag are zero here: static init / previous call's cleanup) ----
    prep_kernel<<<EB, 256>>>(dst, encm, encCnt, remask, remaskCnt);
    scan_kernel<<<1, 1024>>>();
    scatter_kernel<<<EB, 256>>>(src, dst);

    // ---- encoder layer 0 (reads x with enc-token substitution, bit 3) ----
    gemm_elr_kernel<INDIM, true><<<GTC, 256>>>(
        x, enc_fc0, enc_al0, enc_ar0, enc_tok, 3, feat, el, er, feath);
    attn_kernel<<<AB, 256>>>(feath, el, er, enc_b0, h0, 0);

    // ---- encoder layer 1 ----
    gemm_elr_kernel<HDDIM, false><<<GTC, 256>>>(
        h0, enc_fc1, enc_al1, enc_ar1, nullptr, 0, feat, el, er, feath);
    attn_kernel<<<AB, 256>>>(feath, el, er, enc_b1, h1, 0);

    // ---- Es = 0.5*(h0+h1); origin_rep = Es @ W_e2d ----
    gemm_bf16_kernel<HDDIM, INDIM, true, false><<<GTC, 256>>>(h0, h1, 0.5f, W_e2d, rep0);

    // ---- decoder x3, accumulate r1 into accb ----
    cudaMemsetAsync(p_acc, 0, (size_t)NN * HDDIM * sizeof(float));
    for (int i = 0; i < 3; i++) {
        gemm_elr_kernel<INDIM, true><<<GTC, 256>>>(
            rep0, dec_fc0, dec_al0, dec_ar0, dec_tok, i, feat, el, er, feath);
        attn_kernel<<<AB, 256>>>(feath, el, er, dec_b0, r0, 0);

        gemm_elr_kernel<HDDIM, false><<<GTC, 256>>>(
            r0, dec_fc1, dec_al1, dec_ar1, nullptr, 0, feat, el, er, feath);
        attn_kernel<<<AB, 256>>>(feath, el, er, dec_b1, accb, 1);
    }

    // ---- out = (accb/3) @ W_d2c ----
    gemm_bf16_kernel<HDDIM, INDIM, false, true><<<GTC, 256>>>(accb, nullptr, 1.f / 3.f, W_d2c, out);

    // ---- restore g_cnt/g_rflag to zero for the next call ----
    cleanup_kernel<<<(NN + 255) / 256, 256>>>();
}